// round 15
// baseline (speedup 1.0000x reference)
#include <cuda_runtime.h>
#include <cuda_bf16.h>
#include <cstdint>

// ---------------------------------------------------------------------------
// Scratch for per-token segment ranges (T = 132096 here; headroom).
#define MAX_T 140000
__device__ int g_seg_start[MAX_T];
__device__ int g_seg_end[MAX_T];

__global__ void seg_bounds_kernel(const int* __restrict__ idx, int S) {
    int i = blockIdx.x * blockDim.x + threadIdx.x;
    if (i >= S) return;
    int t = idx[i];
    if (i == 0 || idx[i - 1] != t) g_seg_start[t] = i;
    if (i == S - 1 || idx[i + 1] != t) g_seg_end[t] = i + 1;
}

// ---------------------------------------------------------------------------
__device__ __forceinline__ uint32_t smem_to_u32(const void* p) {
    uint32_t a;
    asm("{ .reg .u64 t; cvta.to.shared.u64 t, %1; cvt.u32.u64 %0, t; }"
        : "=r"(a) : "l"(p));
    return a;
}
__device__ __forceinline__ void ldsm_x4(uint32_t* r, uint32_t addr) {
    asm volatile("ldmatrix.sync.aligned.m8n8.x4.shared.b16 {%0,%1,%2,%3}, [%4];"
                 : "=r"(r[0]), "=r"(r[1]), "=r"(r[2]), "=r"(r[3]) : "r"(addr));
}
__device__ __forceinline__ void ldsm_x2(uint32_t& r0, uint32_t& r1, uint32_t addr) {
    asm volatile("ldmatrix.sync.aligned.m8n8.x2.shared.b16 {%0,%1}, [%2];"
                 : "=r"(r0), "=r"(r1) : "r"(addr));
}
__device__ __forceinline__ void hmma16816(float& c0, float& c1, float& c2, float& c3,
                                          uint32_t a0, uint32_t a1, uint32_t a2, uint32_t a3,
                                          uint32_t b0, uint32_t b1) {
    asm volatile(
        "mma.sync.aligned.m16n8k16.row.col.f32.bf16.bf16.f32 "
        "{%0,%1,%2,%3}, {%4,%5,%6,%7}, {%8,%9}, {%0,%1,%2,%3};"
        : "+f"(c0), "+f"(c1), "+f"(c2), "+f"(c3)
        : "r"(a0), "r"(a1), "r"(a2), "r"(a3), "r"(b0), "r"(b1));
}

// mbarrier (sm_90 baseline PTX; fine at compute_103 family-generic)
#define MBAR_INIT(addr, cnt) \
    asm volatile("mbarrier.init.shared.b64 [%0], %1;" \
                 :: "r"((uint32_t)(addr)), "r"((uint32_t)(cnt)) : "memory")
#define MBAR_ARRIVE(addr) \
    asm volatile("mbarrier.arrive.release.cta.shared::cta.b64 _, [%0];" \
                 :: "r"((uint32_t)(addr)) : "memory")
#define MBAR_WAIT_PARITY(addr, par) do {                                        \
    uint32_t _mb = (uint32_t)(addr), _p = (uint32_t)(par), _done;               \
    asm volatile("{\n\t.reg .pred p;\n\t"                                       \
        "mbarrier.try_wait.parity.acquire.cta.shared::cta.b64 p, [%1], %2;\n\t" \
        "selp.b32 %0, 1, 0, p;\n\t}" : "=r"(_done) : "r"(_mb), "r"(_p) : "memory"); \
    if (!_done) {                                                               \
        asm volatile("{\n\t.reg .pred P1;\n\tWL_%=:\n\t"                        \
            "mbarrier.try_wait.parity.acquire.cta.shared::cta.b64 P1, [%0], %1, 0x989680;\n\t" \
            "@P1 bra.uni WD_%=;\n\tbra.uni WL_%=;\n\tWD_%=:\n\t}"               \
            :: "r"(_mb), "r"(_p) : "memory");                                   \
    }                                                                           \
} while (0)

// ---------------------------------------------------------------------------
// Split-bf16 GEMM, deduplicated fragments:
//   tok = th + tl, W = wh + wl;  out = th*wh + th*wl + tl*wh  (drop tl*wl).
// Token tile k-layout [0:32)=th, [32:64)=tl; W tile [0:32)=wh, [32:64)=wl.
// Column pairing -> per-thread 4 consecutive output cols -> STG.128.
//
// PIPELINE (this round's change): no per-tile __syncthreads. 4 token buffers,
// full[k] mbarriers (count = 32 warps). At local tile i a warp: waits
// full[i&3] (parity (i>>2)&1), runs MMA+store, converts gather(i+2) into
// buf[(i+2)&3] and arrives. Safety without free-barriers: reaching tile i
// needs all warps past tile i-2's convert => past MMA(i-2) => done reading
// buf[(i+2)&3]'s old content. Warps may drift up to a tile — no convoy.
static constexpr int TILE_TOK = 128;
static constexpr int ROWB     = 144;                 // bytes per k-row
static constexpr int SW_OFF   = 0;                   // W-split: 512 rows
static constexpr int SB_OFF   = 512 * ROWB;          // bias: 73728
static constexpr int MB_OFF   = SB_OFF + 2048;       // 4 mbarriers: 75776
static constexpr int STBUF    = MB_OFF + 128;        // 75904 (16B aligned)
static constexpr int TBYTES   = TILE_TOK * ROWB;     // 18432
static constexpr int SMEM_TOTAL = STBUF + 4 * TBYTES; // 149632

#define NTHREADS 1024   // 32 warps

template <bool EXACT>
__global__ __launch_bounds__(NTHREADS, 1) void fused_hmma_kernel(
    const float* __restrict__ features,   // [S, 32]
    const float* __restrict__ W,          // [32, 512]
    const float* __restrict__ b,          // [512]
    float* __restrict__ out,              // [T, 512]
    int T, int ntiles)
{
    extern __shared__ char smem[];
    const uint32_t smem_base = smem_to_u32(smem);
    const int tid  = threadIdx.x;
    const int wid  = tid >> 5;            // 0..31
    const int lane = tid & 31;

    // --- Stage W^T split (column-pair permuted) + bias + mbarriers ---
    for (int idx = tid; idx < 32 * 512; idx += NTHREADS) {
        const int f = idx >> 9, h = idx & 511;       // coalesced LDG over h
        const float wv = W[idx];
        const __nv_bfloat16 hb = __float2bfloat16(wv);
        const __nv_bfloat16 lb = __float2bfloat16(wv - __bfloat162float(hb));
        const int g = h >> 4, p = h & 15;
        const int row = g * 16 + ((p >> 1) & 1) * 8 + 2 * (p >> 2) + (p & 1);
        char* r = smem + SW_OFF + row * ROWB;
        *(__nv_bfloat16*)(r + 2 * f)        = hb;    // wh  (k = f)
        *(__nv_bfloat16*)(r + 2 * (32 + f)) = lb;    // wl  (k = 32+f)
    }
    if (tid < 512) *(float*)(smem + SB_OFF + 4 * tid) = b[tid];
    if (tid < 4)  MBAR_INIT(smem_base + MB_OFF + tid * 8, 32);
    __syncthreads();

    // --- Hoist W fragments: 2 tiles (e/o) x 4 k-steps x 2 regs = 16 regs ---
    const int wsl = wid * 16;
    uint32_t breg[2][4][2];
    {
        const uint32_t wb = smem_base + SW_OFF;
        #pragma unroll
        for (int eo = 0; eo < 2; eo++)
            #pragma unroll
            for (int ks = 0; ks < 4; ks++) {
                uint32_t addr = wb + (wsl + eo * 8 + (lane & 7)) * ROWB
                              + (ks * 16 + ((lane >> 3) & 1) * 8) * 2;
                ldsm_x2(breg[eo][ks][0], breg[eo][ks][1], addr);
            }
    }
    const int q = lane & 3;
    const float4 bias4 = *reinterpret_cast<const float4*>(
        smem + SB_OFF + (wsl + 4 * q) * 4);

    if ((int)blockIdx.x >= ntiles) return;   // defensive; grid is clamped
    const int gstride = gridDim.x;
    const int nloc = (ntiles - blockIdx.x + gstride - 1) / gstride;

    // --- Gather / convert (thread: f = lane, token row base = wid) ---
    const int f = lane, trow = wid;
    auto gather = [&](int i, float* ts) {
        const int tok0 = (blockIdx.x + i * gstride) * TILE_TOK;
        #pragma unroll
        for (int j = 0; j < 4; j++) {
            const int tok = tok0 + trow + 32 * j;
            int s0, n;
            if (EXACT || tok < T) {
                s0 = g_seg_start[tok];
                n  = g_seg_end[tok] - s0;
            } else { s0 = 0; n = 0; }
            const float* p = features + (uint32_t)(s0 * 32 + f);
            float a0 = (n > 0) ? __ldcs(p)      : 0.0f;
            float a1 = (n > 1) ? __ldcs(p + 32) : 0.0f;
            float a2 = (n > 2) ? __ldcs(p + 64) : 0.0f;
            float ex = 0.0f;
            for (int si = 3; si < n; si++) ex += __ldcs(p + 32 * si);
            ts[j] = 1e-10f + ((a0 + a1) + (a2 + ex));
        }
    };
    auto convert_arrive = [&](int i, const float* ts) {  // write buf[i&3]
        char* B = smem + STBUF + (i & 3) * TBYTES;
        #pragma unroll
        for (int j = 0; j < 4; j++) {
            const int r = trow + 32 * j;
            const __nv_bfloat16 hb = __float2bfloat16(ts[j]);
            const __nv_bfloat16 lb =
                __float2bfloat16(ts[j] - __bfloat162float(hb));
            char* row = B + r * ROWB;
            *(__nv_bfloat16*)(row + 2 * f)        = hb;  // th
            *(__nv_bfloat16*)(row + 2 * (32 + f)) = lb;  // tl
        }
        __syncwarp();
        if (lane == 0) MBAR_ARRIVE(smem_base + MB_OFF + (i & 3) * 8);
    };

    // MMA + store on buffer (i&3) for local tile i.
    auto mma_store = [&](int i) {
        const uint32_t cur = smem_base + STBUF + (uint32_t)(i & 3) * TBYTES;
        const int tok0 = (blockIdx.x + i * gstride) * TILE_TOK;
        const uint32_t arow0 = cur + (lane & 15) * ROWB + ((lane >> 4) * 8) * 2;
        float* obase = out + (uint32_t)(tok0 + (lane >> 2)) * 512 + wsl + 4 * q;
        int rrow = tok0 + (lane >> 2);

        #pragma unroll 1
        for (int m = 0; m < 8; m++) {
            const uint32_t arow = arow0 + (uint32_t)m * (16 * ROWB);

            float e0 = bias4.x, e1 = bias4.y, e2 = e0, e3 = e1;
            float o0 = bias4.z, o1 = bias4.w, o2 = o0, o3 = o1;

            uint32_t a[8];
            // th fragments (k = 0:32)
            ldsm_x4(a, arow);
            ldsm_x4(a + 4, arow + 32);
            hmma16816(e0, e1, e2, e3, a[0], a[1], a[2], a[3],
                      breg[0][0][0], breg[0][0][1]);
            hmma16816(o0, o1, o2, o3, a[0], a[1], a[2], a[3],
                      breg[1][0][0], breg[1][0][1]);
            hmma16816(e0, e1, e2, e3, a[4], a[5], a[6], a[7],
                      breg[0][1][0], breg[0][1][1]);
            hmma16816(o0, o1, o2, o3, a[4], a[5], a[6], a[7],
                      breg[1][1][0], breg[1][1][1]);
            hmma16816(e0, e1, e2, e3, a[0], a[1], a[2], a[3],
                      breg[0][2][0], breg[0][2][1]);
            hmma16816(o0, o1, o2, o3, a[0], a[1], a[2], a[3],
                      breg[1][2][0], breg[1][2][1]);
            hmma16816(e0, e1, e2, e3, a[4], a[5], a[6], a[7],
                      breg[0][3][0], breg[0][3][1]);
            hmma16816(o0, o1, o2, o3, a[4], a[5], a[6], a[7],
                      breg[1][3][0], breg[1][3][1]);
            // tl fragments (k = 32:64), reuse a[]
            ldsm_x4(a, arow + 64);
            ldsm_x4(a + 4, arow + 96);
            hmma16816(e0, e1, e2, e3, a[0], a[1], a[2], a[3],
                      breg[0][0][0], breg[0][0][1]);
            hmma16816(o0, o1, o2, o3, a[0], a[1], a[2], a[3],
                      breg[1][0][0], breg[1][0][1]);
            hmma16816(e0, e1, e2, e3, a[4], a[5], a[6], a[7],
                      breg[0][1][0], breg[0][1][1]);
            hmma16816(o0, o1, o2, o3, a[4], a[5], a[6], a[7],
                      breg[1][1][0], breg[1][1][1]);

            if (EXACT || rrow < T)
                __stcs(reinterpret_cast<float4*>(obase),
                       make_float4(e0, e1, o0, o1));
            if (EXACT || rrow + 8 < T)
                __stcs(reinterpret_cast<float4*>(obase + 8 * 512),
                       make_float4(e2, e3, o2, o3));
            obase += 16 * 512;
            if (!EXACT) rrow += 16;
        }
    };

    // Per-tile step: wait full, prefetch gather(i+3), MMA, convert (i+2).
    auto step = [&](int i, float* ts_cur, float* ts_nxt) {
        MBAR_WAIT_PARITY(smem_base + MB_OFF + (i & 3) * 8, (i >> 2) & 1);
        if (i + 3 < nloc) gather(i + 3, ts_nxt);
        mma_store(i);
        if (i + 2 < nloc) convert_arrive(i + 2, ts_cur);
    };

    // --- Prologue: fill buffers 0,1; issue gather for 2 ---
    float tsA[4], tsB[4];
    gather(0, tsA);
    convert_arrive(0, tsA);
    if (nloc > 1) { gather(1, tsA); convert_arrive(1, tsA); }
    if (nloc > 2) gather(2, tsA);        // in flight; converted at i=0

    // --- Main loop (unrolled x2 for ts ping-pong) ---
    int i = 0;
    while (true) {
        step(i, tsA, tsB);
        if (++i >= nloc) break;
        step(i, tsB, tsA);
        if (++i >= nloc) break;
    }
}

// ---------------------------------------------------------------------------
extern "C" void kernel_launch(void* const* d_in, const int* in_sizes, int n_in,
                              void* d_out, int out_size) {
    const float* features = (const float*)d_in[0];   // [S, 32]
    const float* W        = (const float*)d_in[1];   // [32, 512]
    const float* b        = (const float*)d_in[2];   // [512]
    const int*   idx      = (const int*)d_in[3];     // [S]
    float*       out      = (float*)d_out;           // [T, 512]

    const int S = in_sizes[3];
    const int T = out_size / 512;
    const int ntiles = (T + TILE_TOK - 1) / TILE_TOK;

    static int nsm = 0;
    if (nsm == 0) {
        // First call is the (non-captured) correctness run; cached afterwards.
        cudaDeviceGetAttribute(&nsm, cudaDevAttrMultiProcessorCount, 0);
        if (nsm <= 0) nsm = 148;
        cudaFuncSetAttribute(fused_hmma_kernel<true>,
                             cudaFuncAttributeMaxDynamicSharedMemorySize,
                             SMEM_TOTAL);
        cudaFuncSetAttribute(fused_hmma_kernel<false>,
                             cudaFuncAttributeMaxDynamicSharedMemorySize,
                             SMEM_TOTAL);
    }

    seg_bounds_kernel<<<(S + 255) / 256, 256>>>(idx, S);

    int grid = nsm;
    if (grid > ntiles) grid = ntiles;
    if (T % TILE_TOK == 0)
        fused_hmma_kernel<true><<<grid, NTHREADS, SMEM_TOTAL>>>(
            features, W, b, out, T, ntiles);
    else
        fused_hmma_kernel<false><<<grid, NTHREADS, SMEM_TOTAL>>>(
            features, W, b, out, T, ntiles);
}